// round 15
// baseline (speedup 1.0000x reference)
#include <cuda_runtime.h>
#include <cstdint>

// Problem constants (B=1, C=1, D=64, H=512, W=512, window 11x11 uniform)
#define WW 512
#define HH 512
#define TH 256          // output rows per block (2 bands)
#define COLS 128        // output cols per block (4 strips)
#define NTHREADS 128
#define RING 16
#define CPAD 129        // padded column dim for bank-conflict-free access
#define C1_ (0.0001f)   // 0.01^2
#define C2_ (0.0009f)   // 0.03^2

__device__ double g_ssim_sum;

__global__ void ssim_zero_kernel() { g_ssim_sum = 0.0; }

__global__ void ssim_finalize_kernel(float* out, float inv_n) {
    out[0] = 1.0f - (float)g_ssim_sum * inv_n;
}

__global__ __launch_bounds__(NTHREADS)
void ssim_main_kernel(const float* __restrict__ x,
                      const float* __restrict__ y,
                      const float* __restrict__ window)
{
    // ring[channel][slot][col]  -- layout gives conflict-free STS (phase A)
    // and conflict-free LDS (phase B); see bank analysis in design notes.
    __shared__ float ring[5][RING][CPAD];
    __shared__ float warpsum[NTHREADS / 32];

    const int t     = threadIdx.x;
    const int strip = blockIdx.x;   // 0..3
    const int band  = blockIdx.y;   // 0..1
    const int z     = blockIdx.z;   // slice (0..D-1)
    const int c0 = strip * COLS;
    const int r0 = band * TH;

    const float s = __ldg(&window[0]);   // 1/121 (uniform window weight)

    const float* __restrict__ xs = x + (size_t)z * (HH * (size_t)WW);
    const float* __restrict__ ys = y + (size_t)z * (HH * (size_t)WW);

    // ---- Phase A thread mapping: row-in-batch = t&3, chunk = t>>2 (4 cols each)
    const int arow   = t & 3;
    const int achunk = t >> 2;           // 0..31
    const int g0     = c0 + achunk * 4;  // first col of this chunk (global)
    const int cl     = achunk * 4;       // first col (local to strip)

    // ---- Phase B running vertical sums (thread owns local column t)
    float vx = 0.f, vy = 0.f, vx2 = 0.f, vy2 = 0.f, vxy = 0.f;
    float acc = 0.f;

    const int NB = (TH + 10 + 3) / 4;    // 67 batches of 4 h-sum rows

    for (int b = 0; b < NB; ++b) {
        const int Rb = r0 - 5 + b * 4;

        // =================== Phase A: horizontal box sums for 4 rows ===========
        {
            const int R    = Rb + arow;
            const int slot = R & (RING - 1);
            if (R >= 0 && R < HH) {
                float ax[20], ay[20];
                const float* __restrict__ xr = xs + (size_t)R * WW;
                const float* __restrict__ yr = ys + (size_t)R * WW;
                if (g0 >= 8 && g0 <= 500) {
                    // fast path: 5 aligned float4 loads per input, cols [g0-8, g0+12)
                    #pragma unroll
                    for (int k = 0; k < 5; ++k) {
                        const float4 fx = *reinterpret_cast<const float4*>(xr + g0 - 8 + 4 * k);
                        const float4 fy = *reinterpret_cast<const float4*>(yr + g0 - 8 + 4 * k);
                        ax[4 * k + 0] = fx.x; ax[4 * k + 1] = fx.y; ax[4 * k + 2] = fx.z; ax[4 * k + 3] = fx.w;
                        ay[4 * k + 0] = fy.x; ay[4 * k + 1] = fy.y; ay[4 * k + 2] = fy.z; ay[4 * k + 3] = fy.w;
                    }
                } else {
                    // image-edge chunks: guarded scalar loads with zero padding
                    #pragma unroll
                    for (int i = 0; i < 20; ++i) {
                        const int c = g0 - 8 + i;
                        const bool ok = (c >= 0) && (c < WW);
                        ax[i] = ok ? __ldg(xr + c) : 0.f;
                        ay[i] = ok ? __ldg(yr + c) : 0.f;
                    }
                }
                // build 11-tap window for col g0 (array idx 3..13)
                float sx = 0.f, sy = 0.f, sx2 = 0.f, sy2 = 0.f, sxy = 0.f;
                #pragma unroll
                for (int i = 3; i <= 13; ++i) {
                    const float a = ax[i], bb = ay[i];
                    sx += a; sy += bb;
                    sx2 = fmaf(a, a, sx2);
                    sy2 = fmaf(bb, bb, sy2);
                    sxy = fmaf(a, bb, sxy);
                }
                ring[0][slot][cl] = sx;  ring[1][slot][cl] = sy;
                ring[2][slot][cl] = sx2; ring[3][slot][cl] = sy2;
                ring[4][slot][cl] = sxy;
                // slide 3 more columns
                #pragma unroll
                for (int j = 1; j < 4; ++j) {
                    float a = ax[13 + j], bb = ay[13 + j];
                    sx += a; sy += bb;
                    sx2 = fmaf(a, a, sx2);
                    sy2 = fmaf(bb, bb, sy2);
                    sxy = fmaf(a, bb, sxy);
                    a = ax[2 + j]; bb = ay[2 + j];
                    sx -= a; sy -= bb;
                    sx2 = fmaf(a, -a, sx2);
                    sy2 = fmaf(bb, -bb, sy2);
                    sxy = fmaf(a, -bb, sxy);
                    ring[0][slot][cl + j] = sx;  ring[1][slot][cl + j] = sy;
                    ring[2][slot][cl + j] = sx2; ring[3][slot][cl + j] = sy2;
                    ring[4][slot][cl + j] = sxy;
                }
            } else {
                // out-of-image row -> zero padding contributes zero h-sums
                #pragma unroll
                for (int j = 0; j < 4; ++j) {
                    ring[0][slot][cl + j] = 0.f; ring[1][slot][cl + j] = 0.f;
                    ring[2][slot][cl + j] = 0.f; ring[3][slot][cl + j] = 0.f;
                    ring[4][slot][cl + j] = 0.f;
                }
            }
        }
        __syncthreads();

        // =================== Phase B: vertical sliding + SSIM ==================
        {
            #pragma unroll
            for (int k = 0; k < 4; ++k) {
                const int R    = Rb + k;
                const int slot = R & (RING - 1);
                vx  += ring[0][slot][t];
                vy  += ring[1][slot][t];
                vx2 += ring[2][slot][t];
                vy2 += ring[3][slot][t];
                vxy += ring[4][slot][t];
                const int r = R - 5;                 // output row candidate
                if (r >= r0 && r < r0 + TH) {
                    // emit SSIM at (r, col)
                    const float t1 = vx * s;         // mu_x
                    const float t2 = vy * s;         // mu_y
                    const float P  = t1 * t2;        // mu_x*mu_y
                    const float Qx = t1 * t1;
                    const float Qy = t2 * t2;
                    const float n1 = fmaf(2.f, P, C1_);
                    const float sxy_ = fmaf(vxy, s, -P);       // sigma_xy
                    const float n2 = fmaf(2.f, sxy_, C2_);
                    const float qq = Qx + Qy;
                    const float d1 = qq + C1_;
                    const float d2 = fmaf(vx2 + vy2, s, C2_ - qq);
                    acc += __fdividef(n1 * n2, d1 * d2);
                    // retire trailing row (r-5) from the vertical window
                    const int slot2 = (r - 5) & (RING - 1);
                    vx  -= ring[0][slot2][t];
                    vy  -= ring[1][slot2][t];
                    vx2 -= ring[2][slot2][t];
                    vy2 -= ring[3][slot2][t];
                    vxy -= ring[4][slot2][t];
                }
            }
        }
        __syncthreads();   // guards ring reads vs next batch's writes
    }

    // ---- block reduction -> global double accumulator
    float v = acc;
    #pragma unroll
    for (int o = 16; o > 0; o >>= 1) v += __shfl_xor_sync(0xffffffffu, v, o);
    if ((t & 31) == 0) warpsum[t >> 5] = v;
    __syncthreads();
    if (t == 0) {
        float bs = 0.f;
        #pragma unroll
        for (int w = 0; w < NTHREADS / 32; ++w) bs += warpsum[w];
        atomicAdd(&g_ssim_sum, (double)bs);
    }
}

extern "C" void kernel_launch(void* const* d_in, const int* in_sizes, int n_in,
                              void* d_out, int out_size)
{
    const float* x = (const float*)d_in[0];
    const float* y = (const float*)d_in[1];
    const float* w = (const float*)d_in[2];
    float* out = (float*)d_out;

    const int D = in_sizes[0] / (HH * WW);   // 64
    const float inv_n = 1.0f / ((float)D * (float)HH * (float)WW);

    ssim_zero_kernel<<<1, 1>>>();

    dim3 grid(WW / COLS, HH / TH, D);        // (4, 2, 64)
    ssim_main_kernel<<<grid, NTHREADS>>>(x, y, w);

    ssim_finalize_kernel<<<1, 1>>>(out, inv_n);
}

// round 16
// speedup vs baseline: 1.0020x; 1.0020x over previous
#include <cuda_runtime.h>
#include <cstdint>

// Problem constants (B=1, C=1, D=64, H=512, W=512, window 11x11 uniform)
#define WW 512
#define HH 512
#define TH 256          // output rows per block (2 bands)
#define COLS 128        // output cols per block (4 strips)
#define NTHREADS 128
#define RING 16
#define CPAD 129        // padded column dim for bank-conflict-free access
#define C1_ (0.0001f)   // 0.01^2
#define C2_ (0.0009f)   // 0.03^2

__device__ double g_ssim_sum;

__global__ void ssim_zero_kernel() { g_ssim_sum = 0.0; }

__global__ void ssim_finalize_kernel(float* out, float inv_n) {
    out[0] = 1.0f - (float)g_ssim_sum * inv_n;
}

__global__ __launch_bounds__(NTHREADS)
void ssim_main_kernel(const float* __restrict__ x,
                      const float* __restrict__ y,
                      const float* __restrict__ window)
{
    // ring[channel][slot][col]  -- layout gives conflict-free STS (phase A)
    // and conflict-free LDS (phase B); see bank analysis in design notes.
    __shared__ float ring[5][RING][CPAD];
    __shared__ float warpsum[NTHREADS / 32];

    const int t     = threadIdx.x;
    const int strip = blockIdx.x;   // 0..3
    const int band  = blockIdx.y;   // 0..1
    const int z     = blockIdx.z;   // slice (0..D-1)
    const int c0 = strip * COLS;
    const int r0 = band * TH;

    const float s = __ldg(&window[0]);   // 1/121 (uniform window weight)

    const float* __restrict__ xs = x + (size_t)z * (HH * (size_t)WW);
    const float* __restrict__ ys = y + (size_t)z * (HH * (size_t)WW);

    // ---- Phase A thread mapping: row-in-batch = t&3, chunk = t>>2 (4 cols each)
    const int arow   = t & 3;
    const int achunk = t >> 2;           // 0..31
    const int g0     = c0 + achunk * 4;  // first col of this chunk (global)
    const int cl     = achunk * 4;       // first col (local to strip)

    // ---- Phase B running vertical sums (thread owns local column t)
    float vx = 0.f, vy = 0.f, vx2 = 0.f, vy2 = 0.f, vxy = 0.f;
    float acc = 0.f;

    const int NB = (TH + 10 + 3) / 4;    // 67 batches of 4 h-sum rows

    for (int b = 0; b < NB; ++b) {
        const int Rb = r0 - 5 + b * 4;

        // =================== Phase A: horizontal box sums for 4 rows ===========
        {
            const int R    = Rb + arow;
            const int slot = R & (RING - 1);
            if (R >= 0 && R < HH) {
                float ax[20], ay[20];
                const float* __restrict__ xr = xs + (size_t)R * WW;
                const float* __restrict__ yr = ys + (size_t)R * WW;
                if (g0 >= 8 && g0 <= 500) {
                    // fast path: 5 aligned float4 loads per input, cols [g0-8, g0+12)
                    #pragma unroll
                    for (int k = 0; k < 5; ++k) {
                        const float4 fx = *reinterpret_cast<const float4*>(xr + g0 - 8 + 4 * k);
                        const float4 fy = *reinterpret_cast<const float4*>(yr + g0 - 8 + 4 * k);
                        ax[4 * k + 0] = fx.x; ax[4 * k + 1] = fx.y; ax[4 * k + 2] = fx.z; ax[4 * k + 3] = fx.w;
                        ay[4 * k + 0] = fy.x; ay[4 * k + 1] = fy.y; ay[4 * k + 2] = fy.z; ay[4 * k + 3] = fy.w;
                    }
                } else {
                    // image-edge chunks: guarded scalar loads with zero padding
                    #pragma unroll
                    for (int i = 0; i < 20; ++i) {
                        const int c = g0 - 8 + i;
                        const bool ok = (c >= 0) && (c < WW);
                        ax[i] = ok ? __ldg(xr + c) : 0.f;
                        ay[i] = ok ? __ldg(yr + c) : 0.f;
                    }
                }
                // build 11-tap window for col g0 (array idx 3..13)
                float sx = 0.f, sy = 0.f, sx2 = 0.f, sy2 = 0.f, sxy = 0.f;
                #pragma unroll
                for (int i = 3; i <= 13; ++i) {
                    const float a = ax[i], bb = ay[i];
                    sx += a; sy += bb;
                    sx2 = fmaf(a, a, sx2);
                    sy2 = fmaf(bb, bb, sy2);
                    sxy = fmaf(a, bb, sxy);
                }
                ring[0][slot][cl] = sx;  ring[1][slot][cl] = sy;
                ring[2][slot][cl] = sx2; ring[3][slot][cl] = sy2;
                ring[4][slot][cl] = sxy;
                // slide 3 more columns
                #pragma unroll
                for (int j = 1; j < 4; ++j) {
                    float a = ax[13 + j], bb = ay[13 + j];
                    sx += a; sy += bb;
                    sx2 = fmaf(a, a, sx2);
                    sy2 = fmaf(bb, bb, sy2);
                    sxy = fmaf(a, bb, sxy);
                    a = ax[2 + j]; bb = ay[2 + j];
                    sx -= a; sy -= bb;
                    sx2 = fmaf(a, -a, sx2);
                    sy2 = fmaf(bb, -bb, sy2);
                    sxy = fmaf(a, -bb, sxy);
                    ring[0][slot][cl + j] = sx;  ring[1][slot][cl + j] = sy;
                    ring[2][slot][cl + j] = sx2; ring[3][slot][cl + j] = sy2;
                    ring[4][slot][cl + j] = sxy;
                }
            } else {
                // out-of-image row -> zero padding contributes zero h-sums
                #pragma unroll
                for (int j = 0; j < 4; ++j) {
                    ring[0][slot][cl + j] = 0.f; ring[1][slot][cl + j] = 0.f;
                    ring[2][slot][cl + j] = 0.f; ring[3][slot][cl + j] = 0.f;
                    ring[4][slot][cl + j] = 0.f;
                }
            }
        }
        __syncthreads();

        // =================== Phase B: vertical sliding + SSIM ==================
        {
            #pragma unroll
            for (int k = 0; k < 4; ++k) {
                const int R    = Rb + k;
                const int slot = R & (RING - 1);
                vx  += ring[0][slot][t];
                vy  += ring[1][slot][t];
                vx2 += ring[2][slot][t];
                vy2 += ring[3][slot][t];
                vxy += ring[4][slot][t];
                const int r = R - 5;                 // output row candidate
                if (r >= r0 && r < r0 + TH) {
                    // emit SSIM at (r, col)
                    const float t1 = vx * s;         // mu_x
                    const float t2 = vy * s;         // mu_y
                    const float P  = t1 * t2;        // mu_x*mu_y
                    const float Qx = t1 * t1;
                    const float Qy = t2 * t2;
                    const float n1 = fmaf(2.f, P, C1_);
                    const float sxy_ = fmaf(vxy, s, -P);       // sigma_xy
                    const float n2 = fmaf(2.f, sxy_, C2_);
                    const float qq = Qx + Qy;
                    const float d1 = qq + C1_;
                    const float d2 = fmaf(vx2 + vy2, s, C2_ - qq);
                    acc += __fdividef(n1 * n2, d1 * d2);
                    // retire trailing row (r-5) from the vertical window
                    const int slot2 = (r - 5) & (RING - 1);
                    vx  -= ring[0][slot2][t];
                    vy  -= ring[1][slot2][t];
                    vx2 -= ring[2][slot2][t];
                    vy2 -= ring[3][slot2][t];
                    vxy -= ring[4][slot2][t];
                }
            }
        }
        __syncthreads();   // guards ring reads vs next batch's writes
    }

    // ---- block reduction -> global double accumulator
    float v = acc;
    #pragma unroll
    for (int o = 16; o > 0; o >>= 1) v += __shfl_xor_sync(0xffffffffu, v, o);
    if ((t & 31) == 0) warpsum[t >> 5] = v;
    __syncthreads();
    if (t == 0) {
        float bs = 0.f;
        #pragma unroll
        for (int w = 0; w < NTHREADS / 32; ++w) bs += warpsum[w];
        atomicAdd(&g_ssim_sum, (double)bs);
    }
}

extern "C" void kernel_launch(void* const* d_in, const int* in_sizes, int n_in,
                              void* d_out, int out_size)
{
    const float* x = (const float*)d_in[0];
    const float* y = (const float*)d_in[1];
    const float* w = (const float*)d_in[2];
    float* out = (float*)d_out;

    const int D = in_sizes[0] / (HH * WW);   // 64
    const float inv_n = 1.0f / ((float)D * (float)HH * (float)WW);

    ssim_zero_kernel<<<1, 1>>>();

    dim3 grid(WW / COLS, HH / TH, D);        // (4, 2, 64)
    ssim_main_kernel<<<grid, NTHREADS>>>(x, y, w);

    ssim_finalize_kernel<<<1, 1>>>(out, inv_n);
}

// round 17
// speedup vs baseline: 1.0287x; 1.0266x over previous
#include <cuda_runtime.h>
#include <cstdint>

// Problem constants (B=1, C=1, D=64, H=512, W=512, window 11x11 uniform)
#define WW 512
#define HH 512
#define TH 128          // output rows per block (4 bands)
#define COLS 128        // output cols per block (4 strips)
#define NTHREADS 128
#define RING 20         // ring depth: makes retire-slot rewrite 2 batches away
#define CPAD 129        // padded column dim (float4 units) for conflict-free banks
#define C1_ (0.0001f)   // 0.01^2
#define C2_ (0.0009f)   // 0.03^2

__device__ double g_ssim_sum;

__global__ void ssim_zero_kernel() { g_ssim_sum = 0.0; }

__global__ void ssim_finalize_kernel(float* out, float inv_n) {
    out[0] = 1.0f - (float)g_ssim_sum * inv_n;
}

__global__ __launch_bounds__(NTHREADS)
void ssim_main_kernel(const float* __restrict__ x,
                      const float* __restrict__ y,
                      const float* __restrict__ window)
{
    // Packed 4-channel ring: {sx, sy, sx2+sy2, sxy} per (row-slot, col).
    // float4 element, 129-stride => conflict-free STS.128 (phase A, 4 slots x
    // 2 col-parity groups per 8-lane phase cover all 32 banks) and
    // conflict-free LDS.128 (phase B, lane t -> banks 4t..4t+3).
    __shared__ float4 ring[RING][CPAD];
    __shared__ float warpsum[NTHREADS / 32];

    const int t     = threadIdx.x;
    const int strip = blockIdx.x;   // 0..3
    const int band  = blockIdx.y;   // 0..3
    const int z     = blockIdx.z;   // slice (0..D-1)
    const int c0 = strip * COLS;
    const int r0 = band * TH;

    const float s = __ldg(&window[0]);   // 1/121 (uniform window weight)

    const float* __restrict__ xs = x + (size_t)z * (HH * (size_t)WW);
    const float* __restrict__ ys = y + (size_t)z * (HH * (size_t)WW);

    // ---- Phase A thread mapping: row-in-batch = t&3, chunk = t>>2 (4 cols each)
    const int arow   = t & 3;
    const int achunk = t >> 2;           // 0..31
    const int g0     = c0 + achunk * 4;  // first col of this chunk (global)
    const int cl     = achunk * 4;       // first col (local to strip)

    // ---- Phase B running vertical sums (thread owns local column t)
    float vx = 0.f, vy = 0.f, v22 = 0.f, vxy = 0.f;
    float acc = 0.f;

    const int NB = (TH + 10 + 3) / 4;    // 35 batches of 4 h-sum rows

    // Incremental slot counters (mod RING, RING=20 so no power-of-2 mask).
    // slot(row) = (row + 20) % 20, valid for row >= -20.
    int sA = ((r0 - 5 + arow) + 20) % RING;   // phase-A slot for this thread's row
    int sAdd = ((r0 - 5) + 20) % RING;        // phase-B add slot (row R)
    int sRet = ((r0 - 5) + 30) % RING;        // phase-B retire slot (row R-10)

    for (int b = 0; b < NB; ++b) {
        const int Rb = r0 - 5 + b * 4;

        // =================== Phase A: horizontal box sums for 4 rows ===========
        {
            const int R = Rb + arow;
            if (R >= 0 && R < HH) {
                float ax[20], ay[20];
                const float* __restrict__ xr = xs + (size_t)R * WW;
                const float* __restrict__ yr = ys + (size_t)R * WW;
                if (g0 >= 8 && g0 <= 500) {
                    // fast path: 5 aligned float4 loads per input, cols [g0-8, g0+12)
                    #pragma unroll
                    for (int k = 0; k < 5; ++k) {
                        const float4 fx = *reinterpret_cast<const float4*>(xr + g0 - 8 + 4 * k);
                        const float4 fy = *reinterpret_cast<const float4*>(yr + g0 - 8 + 4 * k);
                        ax[4 * k + 0] = fx.x; ax[4 * k + 1] = fx.y; ax[4 * k + 2] = fx.z; ax[4 * k + 3] = fx.w;
                        ay[4 * k + 0] = fy.x; ay[4 * k + 1] = fy.y; ay[4 * k + 2] = fy.z; ay[4 * k + 3] = fy.w;
                    }
                } else {
                    // image-edge chunks: guarded scalar loads with zero padding
                    #pragma unroll
                    for (int i = 0; i < 20; ++i) {
                        const int c = g0 - 8 + i;
                        const bool ok = (c >= 0) && (c < WW);
                        ax[i] = ok ? __ldg(xr + c) : 0.f;
                        ay[i] = ok ? __ldg(yr + c) : 0.f;
                    }
                }
                // build 11-tap window for col g0 (array idx 3..13)
                float sx = 0.f, sy = 0.f, s22 = 0.f, sxy = 0.f;
                #pragma unroll
                for (int i = 3; i <= 13; ++i) {
                    const float a = ax[i], bb = ay[i];
                    sx += a; sy += bb;
                    s22 = fmaf(a, a, s22);
                    s22 = fmaf(bb, bb, s22);
                    sxy = fmaf(a, bb, sxy);
                }
                ring[sA][cl] = make_float4(sx, sy, s22, sxy);
                // slide 3 more columns
                #pragma unroll
                for (int j = 1; j < 4; ++j) {
                    float a = ax[13 + j], bb = ay[13 + j];
                    sx += a; sy += bb;
                    s22 = fmaf(a, a, s22);
                    s22 = fmaf(bb, bb, s22);
                    sxy = fmaf(a, bb, sxy);
                    a = ax[2 + j]; bb = ay[2 + j];
                    sx -= a; sy -= bb;
                    s22 = fmaf(a, -a, s22);
                    s22 = fmaf(bb, -bb, s22);
                    sxy = fmaf(a, -bb, sxy);
                    ring[sA][cl + j] = make_float4(sx, sy, s22, sxy);
                }
            } else {
                // out-of-image row -> zero padding contributes zero h-sums
                #pragma unroll
                for (int j = 0; j < 4; ++j)
                    ring[sA][cl + j] = make_float4(0.f, 0.f, 0.f, 0.f);
            }
            sA += 4; if (sA >= RING) sA -= RING;
        }
        __syncthreads();
        // NOTE: no trailing barrier. With RING=20 the earliest slot-reuse
        // hazard (phase-B retire read of row R-10 vs rewrite at row R+10) is
        // 2 batches ahead; the single inter-phase barrier of batch b+1
        // already orders all B(b) before any A(b+2).

        // =================== Phase B: vertical sliding + SSIM ==================
        {
            #pragma unroll
            for (int k = 0; k < 4; ++k) {
                const int R = Rb + k;
                const float4 aq = ring[sAdd][t];
                vx += aq.x; vy += aq.y; v22 += aq.z; vxy += aq.w;
                const int r = R - 5;                 // output row candidate
                if (r >= r0 && r < r0 + TH) {
                    // emit SSIM at (r, col)
                    const float t1 = vx * s;         // mu_x
                    const float t2 = vy * s;         // mu_y
                    const float P  = t1 * t2;        // mu_x*mu_y
                    const float Qx = t1 * t1;
                    const float Qy = t2 * t2;
                    const float n1 = fmaf(2.f, P, C1_);
                    const float sxy_ = fmaf(vxy, s, -P);       // sigma_xy
                    const float n2 = fmaf(2.f, sxy_, C2_);
                    const float qq = Qx + Qy;
                    const float d1 = qq + C1_;
                    const float d2 = fmaf(v22, s, C2_ - qq);
                    acc += __fdividef(n1 * n2, d1 * d2);
                    // retire trailing row (r-5) from the vertical window
                    const float4 dq = ring[sRet][t];
                    vx -= dq.x; vy -= dq.y; v22 -= dq.z; vxy -= dq.w;
                }
                sAdd += 1; if (sAdd >= RING) sAdd -= RING;
                sRet += 1; if (sRet >= RING) sRet -= RING;
            }
        }
    }

    // ---- block reduction -> global double accumulator
    float v = acc;
    #pragma unroll
    for (int o = 16; o > 0; o >>= 1) v += __shfl_xor_sync(0xffffffffu, v, o);
    if ((t & 31) == 0) warpsum[t >> 5] = v;
    __syncthreads();
    if (t == 0) {
        float bs = 0.f;
        #pragma unroll
        for (int w = 0; w < NTHREADS / 32; ++w) bs += warpsum[w];
        atomicAdd(&g_ssim_sum, (double)bs);
    }
}

extern "C" void kernel_launch(void* const* d_in, const int* in_sizes, int n_in,
                              void* d_out, int out_size)
{
    const float* x = (const float*)d_in[0];
    const float* y = (const float*)d_in[1];
    const float* w = (const float*)d_in[2];
    float* out = (float*)d_out;

    const int D = in_sizes[0] / (HH * WW);   // 64
    const float inv_n = 1.0f / ((float)D * (float)HH * (float)WW);

    ssim_zero_kernel<<<1, 1>>>();

    dim3 grid(WW / COLS, HH / TH, D);        // (4, 4, 64)
    ssim_main_kernel<<<grid, NTHREADS>>>(x, y, w);

    ssim_finalize_kernel<<<1, 1>>>(out, inv_n);
}